// round 14
// baseline (speedup 1.0000x reference)
#include <cuda_runtime.h>
#include <cuda_fp16.h>
#include <cstdint>

// ============================================================
// ShiftConv (sm_103 non-'a' target): HMMA mma.sync fp16 GEMM.
// out[b,o,h,w] = bias[o] + sum_s sum_c W[o, s*192+c] * x[b,c,h+dh,w+dw]
// GEMM: C[pix, 192] = A[pix, 960] * W^T, fused A-conversion.
// R14 = R13 fusion with the overhead stripped:
//  - fill remap: thread -> fixed XBUF row (t>>2), 9 consecutive chunks,
//    per-thread precomputed 9-bit validity mask (no div/mod/predicates
//    in the loop).
//  - ONE barrier/iter: convert(it+1) pipelined against MMA(it), XBUF
//    3-stage, AF 2-stage.
// MMA path byte-identical to R10 (at the HMMA.16816.F32 roofline).
// CTA M128xN96, warp 64x48, 128 thr, 3 CTAs/SM.
// ============================================================

#define BATCH 4
#define CCH   192
#define HDIM  256
#define WDIM  256
#define OCH   192
#define KTOT  (5 * CCH)   // 960

// Fragment-major W: index = o*960 + it*32 + p*8 (halfs); 8 halfs cover
// k = it*32 + {2p,2p+1, 2p+8,2p+9, 2p+16,2p+17, 2p+24,2p+25}
__device__ __align__(16) __half g_wf[OCH * KTOT];

// ---------------- helpers ----------------

__device__ __forceinline__ uint32_t smem_to_u32(const void* p) {
    uint32_t a;
    asm("{ .reg .u64 t; cvta.to.shared.u64 t, %1; cvt.u32.u64 %0, t; }"
        : "=r"(a) : "l"(p));
    return a;
}

__device__ __forceinline__ void cp_async16z(uint32_t saddr, const void* gaddr,
                                            unsigned sz) {
    asm volatile("cp.async.cg.shared.global [%0], [%1], 16, %2;"
                 :: "r"(saddr), "l"(gaddr), "r"(sz));
}
#define CP_COMMIT() asm volatile("cp.async.commit_group;" ::: "memory")
#define CP_WAIT1()  asm volatile("cp.async.wait_group 1;" ::: "memory")
#define CP_WAIT2()  asm volatile("cp.async.wait_group 2;" ::: "memory")

__device__ __forceinline__ void ldsm4(uint32_t* r, uint32_t addr) {
    asm volatile("ldmatrix.sync.aligned.m8n8.x4.shared.b16 {%0,%1,%2,%3}, [%4];"
                 : "=r"(r[0]), "=r"(r[1]), "=r"(r[2]), "=r"(r[3]) : "r"(addr));
}

__device__ __forceinline__ float lds_f32(uint32_t addr) {
    float f;
    asm volatile("ld.shared.f32 %0, [%1];" : "=f"(f) : "r"(addr));
    return f;
}

__device__ __forceinline__ void sts128(uint32_t addr, uint32_t a, uint32_t b,
                                       uint32_t c, uint32_t d) {
    asm volatile("st.shared.v4.b32 [%0], {%1,%2,%3,%4};"
                 :: "r"(addr), "r"(a), "r"(b), "r"(c), "r"(d) : "memory");
}

__device__ __forceinline__ void mma16816(float* c, const uint32_t* a,
                                         uint32_t b0, uint32_t b1) {
    asm volatile(
        "mma.sync.aligned.m16n8k16.row.col.f32.f16.f16.f32 "
        "{%0,%1,%2,%3}, {%4,%5,%6,%7}, {%8,%9}, {%0,%1,%2,%3};"
        : "+f"(c[0]), "+f"(c[1]), "+f"(c[2]), "+f"(c[3])
        : "r"(a[0]), "r"(a[1]), "r"(a[2]), "r"(a[3]), "r"(b0), "r"(b1));
}

// ---------------- prep kernel (W only) ----------------

__global__ void prep_w(const float* __restrict__ W) {
    int i = blockIdx.x * blockDim.x + threadIdx.x;   // 192*30*4 = 23040
    if (i >= OCH * 30 * 4) return;
    int p  = i & 3;
    int it = (i >> 2) % 30;
    int o  = i / 120;
    const float* src = W + (size_t)o * KTOT + it * 32 + p * 2;
    __half v[8];
#pragma unroll
    for (int q = 0; q < 4; q++) {
        v[q * 2]     = __float2half(src[q * 8]);
        v[q * 2 + 1] = __float2half(src[q * 8 + 1]);
    }
    *reinterpret_cast<uint4*>(g_wf + (size_t)o * KTOT + it * 32 + p * 8) =
        *reinterpret_cast<uint4*>(v);
}

// ---------------- fused GEMM kernel ----------------
// CTA tile M=128 x N=96, K=960, k-step 32. 128 thr = 4 warps 2(M)x2(N);
// warp tile 64x48. 3 CTAs/SM.
// Smem: AF16 2 x 10240B (128 rows x 80B), XBUF 3 x 18432B
// (32 c-rows x 144 fp32 covering pixels w0-4..w0+139).

static constexpr int A_ROWB   = 80;
static constexpr int AF_SZ    = 128 * A_ROWB;       // 10240
static constexpr int X_OFF    = 2 * AF_SZ;          // 20480
static constexpr int X_ROWB   = 576;                // 144 floats
static constexpr int X_SZ     = 32 * X_ROWB;        // 18432
static constexpr int SMEM_TOT = X_OFF + 3 * X_SZ;   // 75776
static constexpr int KITERS   = 30;

__global__ __launch_bounds__(128, 3)
void shiftconv_gemm(const float* __restrict__ x,
                    const float* __restrict__ bias,
                    float* __restrict__ out) {
    extern __shared__ char smem[];
    uint32_t sb = smem_to_u32(smem);

    int tid = threadIdx.x;
    int wid = tid >> 5;
    int lane = tid & 31;
    int wm = wid >> 1;         // 0..1  (M group of 64)
    int wn = wid & 1;          // 0..1  (N group of 48)

    int lm  = lane >> 3;       // ldmatrix matrix index 0..3
    int lr8 = lane & 7;
    int rowoff = (lm & 1) * 8 + lr8;
    int coloff = (lm >> 1) * 8;    // halfs

    int tile = blockIdx.x;                 // 0..4095
    int w0 = (tile & 1) * 128;
    int h  = (tile >> 1) & 255;
    int b  = (tile >> 9) & 3;
    int nh = tile >> 11;                   // N half SLOWEST -> W locality
    int o0 = nh * 96;

    const char* xb = reinterpret_cast<const char*>(x);

    // ---- fill role (hoisted): row = tid>>2, cols (tid&3)*9 + 0..8 ----
    int frow = tid >> 2;                   // XBUF c-row 0..31
    int col0 = (tid & 3) * 9;              // first 16B chunk
    // per-thread float index base (chunk j2 adds j2*4)
    int g0 = ((b * CCH + frow) * HDIM + h) * WDIM + (w0 - 4) + col0 * 4;
    // validity mask over j2 (w boundary): chunk col16 = col0 + j2
    unsigned vmask = 0x1FFu;
    if (w0 == 0 && col0 == 0) vmask &= ~1u;            // col16 0 invalid
    if (w0 == 128 && col0 == 27) vmask &= 0x3Fu;       // col16 33,34,35
    uint32_t xfill = sb + X_OFF + frow * X_ROWB + col0 * 16;

    // ---- B fragment base pointer (per lane) ----
    const __half* wf0 = g_wf + (size_t)(o0 + wn * 48 + (lane >> 2)) * KTOT
                        + (lane & 3) * 8;

    float acc[4][3][2][4] = {};

    auto issueX = [&](int j) {
        int seg = (j * 43691) >> 18;       // j/6 for j<32
        int c0 = (j - seg * 6) * 32;
        int dh = (seg == 3) - (seg == 4);
        int hs = h + dh;
        bool rv = (hs >= 0) && (hs < HDIM);
        int ga = g0 + c0 * (HDIM * WDIM) + (rv ? dh * WDIM : 0);
        unsigned m = rv ? vmask : 0u;
        uint32_t xd = xfill + (j % 3) * X_SZ;
        const char* gp = xb + (size_t)ga * 4;
#pragma unroll
        for (int j2 = 0; j2 < 9; j2++) {
            unsigned sz = ((m >> j2) & 1u) ? 16u : 0u;
            cp_async16z(xd + j2 * 16, gp + j2 * 16, sz);
        }
    };

    // convert XBUF[j%3] (fp32, pixel = float idx p+4+dw) -> AF[j&1]
    auto convertA = [&](int j) {
        int seg = (j * 43691) >> 18;
        int dw = (seg == 1) - (seg == 2);
        uint32_t xs = sb + X_OFF + (j % 3) * X_SZ + (tid + 4 + dw) * 4;
        uint32_t ad = sb + (j & 1) * AF_SZ + tid * A_ROWB;
#pragma unroll
        for (int hv = 0; hv < 2; hv++) {
            uint32_t h2[8];
#pragma unroll
            for (int c2 = 0; c2 < 8; c2++) {
                int c = hv * 16 + c2 * 2;
                float f0 = lds_f32(xs + c * X_ROWB);
                float f1 = lds_f32(xs + (c + 1) * X_ROWB);
                __half2 p = __floats2half2_rn(f0, f1);
                h2[c2] = *reinterpret_cast<uint32_t*>(&p);
            }
            sts128(ad + hv * 32,      h2[0], h2[1], h2[2], h2[3]);
            sts128(ad + hv * 32 + 16, h2[4], h2[5], h2[6], h2[7]);
        }
    };

    // ---- prologue: fills 0,1,2; convert 0 ----
    issueX(0); CP_COMMIT();
    issueX(1); CP_COMMIT();
    issueX(2); CP_COMMIT();
    CP_WAIT2();                // group 0 complete
    __syncthreads();
    convertA(0);               // AF[0] (ordered before loop's first bar)

#pragma unroll 1
    for (int it = 0; it < KITERS; ++it) {
        // B fragments for MMA(it): 6 x LDG.128, before the wait.
        uint32_t bf[3][2][4];
#pragma unroll
        for (int nj = 0; nj < 3; nj++)
#pragma unroll
            for (int hf = 0; hf < 2; hf++) {
                const uint4* pB = reinterpret_cast<const uint4*>(
                    wf0 + (size_t)(nj * 16 + hf * 8) * KTOT + it * 32);
                uint4 v = __ldg(pB);
                bf[nj][hf][0] = v.x; bf[nj][hf][1] = v.y;
                bf[nj][hf][2] = v.z; bf[nj][hf][3] = v.w;
            }

        CP_WAIT1();            // groups <= it+2 may be pending 1 -> it+1 done
        __syncthreads();       // XBUF[it+1] ready; convert(it)/MMA(it-1) done

        if (it + 1 < KITERS) convertA(it + 1);
        if (it + 3 < KITERS) issueX(it + 3);
        CP_COMMIT();           // unconditional: keeps group numbering aligned

        uint32_t Ab = sb + (it & 1) * AF_SZ;

#pragma unroll
        for (int kk = 0; kk < 2; kk++) {
#pragma unroll
            for (int mh = 0; mh < 2; mh++) {
                uint32_t afr[2][4];
#pragma unroll
                for (int m2 = 0; m2 < 2; m2++) {
                    int row = wm * 64 + (mh * 2 + m2) * 16 + rowoff;
                    int col = kk * 16 + coloff;
                    ldsm4(afr[m2], Ab + row * A_ROWB + col * 2);
                }
#pragma unroll
                for (int m2 = 0; m2 < 2; m2++) {
                    int mi = mh * 2 + m2;
#pragma unroll
                    for (int nj = 0; nj < 3; nj++) {
                        mma16816(acc[mi][nj][0], afr[m2],
                                 bf[nj][0][kk * 2], bf[nj][0][kk * 2 + 1]);
                        mma16816(acc[mi][nj][1], afr[m2],
                                 bf[nj][1][kk * 2], bf[nj][1][kk * 2 + 1]);
                    }
                }
            }
        }
    }

    // ---- epilogue: direct STG (8 consecutive pixels x 4B per store row) ----
    int g8 = lane >> 2;
    int q  = lane & 3;
    size_t out_hw = (size_t)h * WDIM + w0;
#pragma unroll
    for (int mi = 0; mi < 4; mi++) {
        int r0 = wm * 64 + mi * 16 + g8;
#pragma unroll
        for (int nj = 0; nj < 3; nj++)
#pragma unroll
            for (int hf = 0; hf < 2; hf++) {
                int o = o0 + wn * 48 + nj * 16 + hf * 8 + 2 * q;
                float bz0 = __ldg(bias + o);
                float bz1 = __ldg(bias + o + 1);
                float* p0 = out + ((size_t)(b * OCH + o)) * (HDIM * WDIM)
                            + out_hw;
                float* p1 = p0 + (size_t)(HDIM * WDIM);
                p0[r0]     = acc[mi][nj][hf][0] + bz0;
                p1[r0]     = acc[mi][nj][hf][1] + bz1;
                p0[r0 + 8] = acc[mi][nj][hf][2] + bz0;
                p1[r0 + 8] = acc[mi][nj][hf][3] + bz1;
            }
    }
}

// ---------------- launch ----------------

extern "C" void kernel_launch(void* const* d_in, const int* in_sizes, int n_in,
                              void* d_out, int out_size) {
    const float* x = (const float*)d_in[0];    // [4,192,256,256]
    const float* W = (const float*)d_in[1];    // [192, 960]
    const float* bias = (const float*)d_in[2]; // [192]
    float* out = (float*)d_out;

    {
        int n = OCH * 30 * 4;
        prep_w<<<(n + 255) / 256, 256>>>(W);
    }
    cudaFuncSetAttribute(shiftconv_gemm,
                         cudaFuncAttributeMaxDynamicSharedMemorySize, SMEM_TOT);
    shiftconv_gemm<<<BATCH * HDIM * 2 * 2, 128, SMEM_TOT>>>(x, bias, out);
}

// round 15
// speedup vs baseline: 1.7016x; 1.7016x over previous
#include <cuda_runtime.h>
#include <cuda_fp16.h>
#include <cstdint>

// ============================================================
// ShiftConv (sm_103 non-'a' target): HMMA mma.sync fp16 GEMM.
// out[b,o,h,w] = bias[o] + sum_s sum_c W[o, s*192+c] * x[b,c,h+dh,w+dw]
// GEMM: C[pix, 192] = A[pix, 960] * W^T. A = shifted gather from padded
// pixel-major fp16 x (cp.async smem + ldmatrix). B = fragment-major W in
// gmem, 6x LDG.128 per warp-iter straight into mma layout.
// R15: GEMM = R10 verbatim (measured AT the HMMA.16816.F32 issue
// roofline, 0.25/cyc/SM). prep_x write phase widened to uint4 (16B)
// stores — 4 threads = 64B contiguous run, conflict-free smem reads.
// Fusion branch (R13/R14) closed: it serialized the MMA critical path.
// ============================================================

#define BATCH 4
#define CCH   192
#define HDIM  256
#define WDIM  256
#define HP    258
#define WP    258
#define OCH   192
#define KTOT  (5 * CCH)   // 960

static constexpr int XPAD_ELEMS = BATCH * HP * WP * CCH;

__device__ __align__(16) __half g_xh[XPAD_ELEMS];
// Fragment-major W: index = o*960 + it*32 + p*8 (halfs); 8 halfs cover
// k = it*32 + {2p,2p+1, 2p+8,2p+9, 2p+16,2p+17, 2p+24,2p+25}
__device__ __align__(16) __half g_wf[OCH * KTOT];

// ---------------- helpers ----------------

__device__ __forceinline__ uint32_t smem_to_u32(const void* p) {
    uint32_t a;
    asm("{ .reg .u64 t; cvta.to.shared.u64 t, %1; cvt.u32.u64 %0, t; }"
        : "=r"(a) : "l"(p));
    return a;
}

__device__ __forceinline__ void cp_async16(uint32_t saddr, const void* gaddr) {
    asm volatile("cp.async.cg.shared.global [%0], [%1], 16;"
                 :: "r"(saddr), "l"(gaddr));
}
#define CP_COMMIT() asm volatile("cp.async.commit_group;" ::: "memory")
#define CP_WAIT2()  asm volatile("cp.async.wait_group 2;" ::: "memory")

__device__ __forceinline__ void ldsm4(uint32_t* r, uint32_t addr) {
    asm volatile("ldmatrix.sync.aligned.m8n8.x4.shared.b16 {%0,%1,%2,%3}, [%4];"
                 : "=r"(r[0]), "=r"(r[1]), "=r"(r[2]), "=r"(r[3]) : "r"(addr));
}

__device__ __forceinline__ void mma16816(float* c, const uint32_t* a,
                                         uint32_t b0, uint32_t b1) {
    asm volatile(
        "mma.sync.aligned.m16n8k16.row.col.f32.f16.f16.f32 "
        "{%0,%1,%2,%3}, {%4,%5,%6,%7}, {%8,%9}, {%0,%1,%2,%3};"
        : "+f"(c[0]), "+f"(c[1]), "+f"(c[2]), "+f"(c[3])
        : "r"(a[0]), "r"(a[1]), "r"(a[2]), "r"(a[3]), "r"(b0), "r"(b1));
}

// ---------------- prep kernels ----------------

__global__ void prep_border() {
    const int per_b = 4 * WP * CCH;
    int i = blockIdx.x * blockDim.x + threadIdx.x;
    if (i >= BATCH * per_b) return;
    int b = i / per_b;
    int r = i % per_b;
    int line = r / (WP * CCH);
    int j = r % (WP * CCH);
    int pos = j / CCH;
    int c = j % CCH;
    int hh, ww;
    if      (line == 0) { hh = 0;      ww = pos; }
    else if (line == 1) { hh = HP - 1; ww = pos; }
    else if (line == 2) { hh = pos;    ww = 0;   }
    else                { hh = pos;    ww = WP - 1; }
    g_xh[(((size_t)b * HP + hh) * WP + ww) * CCH + c] = __float2half(0.0f);
}

// Transpose [B,C,H,W] fp32 -> padded pixel-major [B,HP,WP,C] fp16.
// Block = 32 channels x 128 w. float4 reads; uint4 (8-half) writes:
// thread -> one pixel x 8-channel group, 4 threads = 64B contiguous.
__global__ void prep_x(const float* __restrict__ x) {
    __shared__ float tile[32][129];
    int w0 = blockIdx.x * 128;
    int c0 = blockIdx.y * 32;
    int bh = blockIdx.z;
    int b = bh >> 8, h = bh & 255;
    int tid = threadIdx.x;           // 256
    int tx = tid & 31;
    int ty = tid >> 5;

    // ---- read: 32 c-rows x 128 w, float4 per thread per pass ----
#pragma unroll
    for (int i = 0; i < 4; i++) {
        int c = c0 + ty + i * 8;
        float4 v = *reinterpret_cast<const float4*>(
            x + (((size_t)b * CCH + c) * HDIM + h) * WDIM + w0 + tx * 4);
        tile[ty + i * 8][tx * 4 + 0] = v.x;
        tile[ty + i * 8][tx * 4 + 1] = v.y;
        tile[ty + i * 8][tx * 4 + 2] = v.z;
        tile[ty + i * 8][tx * 4 + 3] = v.w;
    }
    __syncthreads();

    // ---- write: (w, 8-ch group) per slot; uint4 per thread ----
    // 128 w x 4 groups = 512 slots / 256 threads = 2 iters.
#pragma unroll
    for (int j = 0; j < 2; j++) {
        int idx = tid + j * 256;     // 0..511
        int w  = idx >> 2;           // 0..127
        int cg = (idx & 3) * 8;      // 0,8,16,24
        __half2 p0 = __floats2half2_rn(tile[cg + 0][w], tile[cg + 1][w]);
        __half2 p1 = __floats2half2_rn(tile[cg + 2][w], tile[cg + 3][w]);
        __half2 p2 = __floats2half2_rn(tile[cg + 4][w], tile[cg + 5][w]);
        __half2 p3 = __floats2half2_rn(tile[cg + 6][w], tile[cg + 7][w]);
        size_t dst = (((size_t)b * HP + (h + 1)) * WP + (w0 + w + 1)) * CCH
                     + c0 + cg;
        uint4 v;
        v.x = *reinterpret_cast<uint32_t*>(&p0);
        v.y = *reinterpret_cast<uint32_t*>(&p1);
        v.z = *reinterpret_cast<uint32_t*>(&p2);
        v.w = *reinterpret_cast<uint32_t*>(&p3);
        *reinterpret_cast<uint4*>(g_xh + dst) = v;
    }
}

// Pack W fp32 [o,k] into fragment-major fp16 g_wf.
__global__ void prep_w(const float* __restrict__ W) {
    int i = blockIdx.x * blockDim.x + threadIdx.x;   // 192*30*4 = 23040
    if (i >= OCH * 30 * 4) return;
    int p  = i & 3;
    int it = (i >> 2) % 30;
    int o  = i / 120;
    const float* src = W + (size_t)o * KTOT + it * 32 + p * 2;
    __half v[8];
#pragma unroll
    for (int q = 0; q < 4; q++) {
        v[q * 2]     = __float2half(src[q * 8]);
        v[q * 2 + 1] = __float2half(src[q * 8 + 1]);
    }
    *reinterpret_cast<uint4*>(g_wf + (size_t)o * KTOT + it * 32 + p * 8) =
        *reinterpret_cast<uint4*>(v);
}

// ---------------- main GEMM kernel (R10, at HMMA roofline) ----------------
// CTA tile M=128 pixels x N=96 outputs, K=960, k-step 32, 4-stage cp.async
// for A. 128 threads = 4 warps 2(M)x2(N); warp tile 64x48. 3 CTAs/SM.

static constexpr int STAGES   = 4;
static constexpr int A_ROWB   = 80;                 // 40 halfs (32 + 8 pad)
static constexpr int A_SZ     = 128 * A_ROWB;       // 10240 B / stage
static constexpr int SMEM_TOT = STAGES * A_SZ;      // 40960
static constexpr int KITERS   = 30;

__global__ __launch_bounds__(128, 3)
void shiftconv_gemm(const float* __restrict__ bias, float* __restrict__ out) {
    extern __shared__ char smem[];
    uint32_t sb = smem_to_u32(smem);

    int tid = threadIdx.x;
    int wid = tid >> 5;
    int lane = tid & 31;
    int wm = wid >> 1;         // 0..1  (M group of 64)
    int wn = wid & 1;          // 0..1  (N group of 48)

    int lm  = lane >> 3;       // ldmatrix matrix index 0..3
    int lr8 = lane & 7;
    int rowoff = (lm & 1) * 8 + lr8;
    int coloff = (lm >> 1) * 8;    // halfs

    int tile = blockIdx.x;                 // 0..4095
    int w0 = (tile & 1) * 128;
    int h  = (tile >> 1) & 255;
    int b  = (tile >> 9) & 3;
    int nh = tile >> 11;                   // N half SLOWEST -> W locality
    int o0 = nh * 96;

    // ---- A fill: one base ptr + int32 per-segment offsets ----
    int ar = tid;                          // pixel row 0..127
    uint32_t aoff[5];
#pragma unroll
    for (int s = 0; s < 5; s++) {
        int dh = (s == 3) - (s == 4);
        int dw = (s == 1) - (s == 2);
        aoff[s] = (uint32_t)((((b * HP) + (h + 1 + dh)) * WP
                              + (w0 + ar + 1 + dw)) * CCH);
    }
    uint32_t a_smem = sb + ar * A_ROWB;

    // ---- B fragment base pointer (per lane) ----
    const __half* wf0 = g_wf + (size_t)(o0 + wn * 48 + (lane >> 2)) * KTOT
                        + (lane & 3) * 8;

    float acc[4][3][2][4] = {};

    auto issueA = [&](int it) {
        int seg = (it * 43691) >> 18;      // it/6 for it<30
        int c0 = (it - seg * 6) * 32;
        const char* ga = reinterpret_cast<const char*>(g_xh + aoff[seg] + c0);
        uint32_t sa = a_smem + (it & 3) * A_SZ;
#pragma unroll
        for (int j = 0; j < 4; j++)
            cp_async16(sa + j * 16, ga + j * 16);
    };

#pragma unroll
    for (int s = 0; s < STAGES - 1; s++) { issueA(s); CP_COMMIT(); }

#pragma unroll 1
    for (int it = 0; it < KITERS; ++it) {
        // B fragments for this iter: 6 x LDG.128, issued before the wait
        // so L2 latency overlaps CP_WAIT + barrier.
        uint32_t bf[3][2][4];
#pragma unroll
        for (int nj = 0; nj < 3; nj++)
#pragma unroll
            for (int hf = 0; hf < 2; hf++) {
                const uint4* pB = reinterpret_cast<const uint4*>(
                    wf0 + (size_t)(nj * 16 + hf * 8) * KTOT + it * 32);
                uint4 v = __ldg(pB);
                bf[nj][hf][0] = v.x; bf[nj][hf][1] = v.y;
                bf[nj][hf][2] = v.z; bf[nj][hf][3] = v.w;
            }

        CP_WAIT2();
        __syncthreads();   // stage it&3 ready; all warps done reading (it-1)&3

        if (it + STAGES - 1 < KITERS) issueA(it + STAGES - 1);
        CP_COMMIT();

        uint32_t Ab = sb + (it & 3) * A_SZ;

#pragma unroll
        for (int kk = 0; kk < 2; kk++) {
            // mi processed in halves of 2 to keep only 8 afr regs live
#pragma unroll
            for (int mh = 0; mh < 2; mh++) {
                uint32_t afr[2][4];
#pragma unroll
                for (int m2 = 0; m2 < 2; m2++) {
                    int row = wm * 64 + (mh * 2 + m2) * 16 + rowoff;
                    int col = kk * 16 + coloff;
                    ldsm4(afr[m2], Ab + row * A_ROWB + col * 2);
                }
#pragma unroll
                for (int m2 = 0; m2 < 2; m2++) {
                    int mi = mh * 2 + m2;
#pragma unroll
                    for (int nj = 0; nj < 3; nj++) {
                        mma16816(acc[mi][nj][0], afr[m2],
                                 bf[nj][0][kk * 2], bf[nj][0][kk * 2 + 1]);
                        mma16816(acc[mi][nj][1], afr[m2],
                                 bf[nj][1][kk * 2], bf[nj][1][kk * 2 + 1]);
                    }
                }
            }
        }
    }

    // ---- epilogue: direct STG (8 consecutive pixels x 4B per store row) ----
    int g8 = lane >> 2;       // 0..7 pixel sub-row
    int q  = lane & 3;        // o pair selector
    size_t out_hw = (size_t)h * WDIM + w0;
#pragma unroll
    for (int mi = 0; mi < 4; mi++) {
        int r0 = wm * 64 + mi * 16 + g8;
#pragma unroll
        for (int nj = 0; nj < 3; nj++)
#pragma unroll
            for (int hf = 0; hf < 2; hf++) {
                int o = o0 + wn * 48 + nj * 16 + hf * 8 + 2 * q;
                float bz0 = __ldg(bias + o);
                float bz1 = __ldg(bias + o + 1);
                float* p0 = out + ((size_t)(b * OCH + o)) * (HDIM * WDIM)
                            + out_hw;
                float* p1 = p0 + (size_t)(HDIM * WDIM);
                p0[r0]     = acc[mi][nj][hf][0] + bz0;
                p1[r0]     = acc[mi][nj][hf][1] + bz1;
                p0[r0 + 8] = acc[mi][nj][hf][2] + bz0;
                p1[r0 + 8] = acc[mi][nj][hf][3] + bz1;
            }
    }
}

// ---------------- launch ----------------

extern "C" void kernel_launch(void* const* d_in, const int* in_sizes, int n_in,
                              void* d_out, int out_size) {
    const float* x = (const float*)d_in[0];    // [4,192,256,256]
    const float* W = (const float*)d_in[1];    // [192, 960]
    const float* bias = (const float*)d_in[2]; // [192]
    float* out = (float*)d_out;

    {
        int n = BATCH * 4 * WP * CCH;
        prep_border<<<(n + 255) / 256, 256>>>();
    }
    prep_x<<<dim3(WDIM / 128, CCH / 32, BATCH * HDIM), 256>>>(x);
    {
        int n = OCH * 30 * 4;
        prep_w<<<(n + 255) / 256, 256>>>(W);
    }
    cudaFuncSetAttribute(shiftconv_gemm,
                         cudaFuncAttributeMaxDynamicSharedMemorySize, SMEM_TOT);
    shiftconv_gemm<<<BATCH * HDIM * 2 * 2, 128, SMEM_TOT>>>(bias, out);
}

// round 16
// speedup vs baseline: 1.7451x; 1.0256x over previous
#include <cuda_runtime.h>
#include <cuda_fp16.h>
#include <cstdint>

// ============================================================
// ShiftConv (sm_103 non-'a' target): HMMA mma.sync fp16 GEMM.
// out[b,o,h,w] = bias[o] + sum_s sum_c W[o, s*192+c] * x[b,c,h+dh,w+dw]
// GEMM: C[pix, 192] = A[pix, 960] * W^T. A = shifted gather from padded
// pixel-major fp16 x (cp.async smem + ldmatrix). B = fragment-major W in
// gmem, 6x LDG.128 per warp-iter straight into mma layout.
// R16: GEMM = R10 verbatim (AT the HMMA.16816.F32 issue roofline,
// 0.25/cyc/SM). Prep consolidated into ONE launch (prep_all) and the
// transpose made bank-conflict-free both phases via channel-row
// permutation perm(c)=((c&3)<<3)|(c>>2) in a float4[32x33] tile
// (STS.128 write, verified distinct-bank read).
// ============================================================

#define BATCH 4
#define CCH   192
#define HDIM  256
#define WDIM  256
#define HP    258
#define WP    258
#define OCH   192
#define KTOT  (5 * CCH)   // 960

static constexpr int XPAD_ELEMS = BATCH * HP * WP * CCH;

__device__ __align__(16) __half g_xh[XPAD_ELEMS];
// Fragment-major W: index = o*960 + it*32 + p*8 (halfs); 8 halfs cover
// k = it*32 + {2p,2p+1, 2p+8,2p+9, 2p+16,2p+17, 2p+24,2p+25}
__device__ __align__(16) __half g_wf[OCH * KTOT];

// ---------------- helpers ----------------

__device__ __forceinline__ uint32_t smem_to_u32(const void* p) {
    uint32_t a;
    asm("{ .reg .u64 t; cvta.to.shared.u64 t, %1; cvt.u32.u64 %0, t; }"
        : "=r"(a) : "l"(p));
    return a;
}

__device__ __forceinline__ void cp_async16(uint32_t saddr, const void* gaddr) {
    asm volatile("cp.async.cg.shared.global [%0], [%1], 16;"
                 :: "r"(saddr), "l"(gaddr));
}
#define CP_COMMIT() asm volatile("cp.async.commit_group;" ::: "memory")
#define CP_WAIT2()  asm volatile("cp.async.wait_group 2;" ::: "memory")

__device__ __forceinline__ void ldsm4(uint32_t* r, uint32_t addr) {
    asm volatile("ldmatrix.sync.aligned.m8n8.x4.shared.b16 {%0,%1,%2,%3}, [%4];"
                 : "=r"(r[0]), "=r"(r[1]), "=r"(r[2]), "=r"(r[3]) : "r"(addr));
}

__device__ __forceinline__ void mma16816(float* c, const uint32_t* a,
                                         uint32_t b0, uint32_t b1) {
    asm volatile(
        "mma.sync.aligned.m16n8k16.row.col.f32.f16.f16.f32 "
        "{%0,%1,%2,%3}, {%4,%5,%6,%7}, {%8,%9}, {%0,%1,%2,%3};"
        : "+f"(c[0]), "+f"(c[1]), "+f"(c[2]), "+f"(c[3])
        : "r"(a[0]), "r"(a[1]), "r"(a[2]), "r"(a[3]), "r"(b0), "r"(b1));
}

// ---------------- fused prep kernel ----------------
// blocks [0, 12288): x transpose+convert (2 wblk x 6 cblk x 1024 bh)
// blocks [12288, 15384): border zeroing (3096 x 256 = 792576 elems)
// blocks [15384, 15474): W fragment pack (90 x 256 = 23040)

static constexpr int NB_T = 12288;
static constexpr int NB_B = 3096;
static constexpr int NB_W = 90;
static constexpr int NB_ALL = NB_T + NB_B + NB_W;

__global__ __launch_bounds__(256)
void prep_all(const float* __restrict__ x, const float* __restrict__ W) {
    __shared__ float4 tile4[32 * 33];    // row stride 33 chunks (132 floats)
    int blk = blockIdx.x;
    int tid = threadIdx.x;               // 256

    if (blk < NB_T) {
        // ---- transpose: blk = ((bh*6 + cblk) << 1) | wblk ----
        int wblk = blk & 1;
        int rest = blk >> 1;             // 0..6143
        int cblk = rest % 6;
        int bh   = rest / 6;             // 0..1023
        int b = bh >> 8, h = bh & 255;
        int w0 = wblk * 128, c0 = cblk * 32;
        int tx = tid & 31;               // w-quad 0..31
        int ty = tid >> 5;               // 0..7

        // write phase: channel row -> permuted smem row; STS.128,
        // per-8-lane phase chunks distinct mod 8 -> conflict-free.
#pragma unroll
        for (int i = 0; i < 4; i++) {
            int row = ty + i * 8;        // channel-in-tile 0..31
            float4 v = *reinterpret_cast<const float4*>(
                x + (((size_t)b * CCH + c0 + row) * HDIM + h) * WDIM
                  + w0 + tx * 4);
            int pr = ((row & 3) << 3) | (row >> 2);
            tile4[pr * 33 + tx] = v;
        }
        __syncthreads();

        // read phase: bank = (8*(lane&3) + (lane>>2) + const) mod 32 —
        // all 32 lanes distinct -> conflict-free scalar LDS.
        const float* tf = reinterpret_cast<const float*>(tile4);
#pragma unroll
        for (int j = 0; j < 2; j++) {
            int idx = tid + j * 256;     // 0..511
            int w  = idx >> 2;           // 0..127
            int cg = (idx & 3) * 8;      // 0,8,16,24
            float f[8];
#pragma unroll
            for (int i = 0; i < 8; i++) {
                int c = cg + i;
                int pr = ((c & 3) << 3) | (c >> 2);
                f[i] = tf[(pr * 33 + (w >> 2)) * 4 + (w & 3)];
            }
            __half2 p0 = __floats2half2_rn(f[0], f[1]);
            __half2 p1 = __floats2half2_rn(f[2], f[3]);
            __half2 p2 = __floats2half2_rn(f[4], f[5]);
            __half2 p3 = __floats2half2_rn(f[6], f[7]);
            size_t dst = (((size_t)b * HP + (h + 1)) * WP + (w0 + w + 1))
                         * CCH + c0 + cg;
            uint4 v;
            v.x = *reinterpret_cast<uint32_t*>(&p0);
            v.y = *reinterpret_cast<uint32_t*>(&p1);
            v.z = *reinterpret_cast<uint32_t*>(&p2);
            v.w = *reinterpret_cast<uint32_t*>(&p3);
            *reinterpret_cast<uint4*>(g_xh + dst) = v;
        }
    } else if (blk < NB_T + NB_B) {
        // ---- border zeroing ----
        const int per_b = 4 * WP * CCH;
        int i = (blk - NB_T) * 256 + tid;
        int b = i / per_b;
        int r = i % per_b;
        int line = r / (WP * CCH);
        int j = r % (WP * CCH);
        int pos = j / CCH;
        int c = j % CCH;
        int hh, ww;
        if      (line == 0) { hh = 0;      ww = pos; }
        else if (line == 1) { hh = HP - 1; ww = pos; }
        else if (line == 2) { hh = pos;    ww = 0;   }
        else                { hh = pos;    ww = WP - 1; }
        g_xh[(((size_t)b * HP + hh) * WP + ww) * CCH + c] =
            __float2half(0.0f);
    } else {
        // ---- W fragment pack ----
        int i = (blk - NB_T - NB_B) * 256 + tid;   // 0..23039
        int p  = i & 3;
        int it = (i >> 2) % 30;
        int o  = i / 120;
        const float* src = W + (size_t)o * KTOT + it * 32 + p * 2;
        __half v[8];
#pragma unroll
        for (int q = 0; q < 4; q++) {
            v[q * 2]     = __float2half(src[q * 8]);
            v[q * 2 + 1] = __float2half(src[q * 8 + 1]);
        }
        *reinterpret_cast<uint4*>(g_wf + (size_t)o * KTOT + it * 32 + p * 8) =
            *reinterpret_cast<uint4*>(v);
    }
}

// ---------------- main GEMM kernel (R10, at HMMA roofline) ----------------
// CTA tile M=128 pixels x N=96 outputs, K=960, k-step 32, 4-stage cp.async
// for A. 128 threads = 4 warps 2(M)x2(N); warp tile 64x48. 3 CTAs/SM.

static constexpr int STAGES   = 4;
static constexpr int A_ROWB   = 80;                 // 40 halfs (32 + 8 pad)
static constexpr int A_SZ     = 128 * A_ROWB;       // 10240 B / stage
static constexpr int SMEM_TOT = STAGES * A_SZ;      // 40960
static constexpr int KITERS   = 30;

__global__ __launch_bounds__(128, 3)
void shiftconv_gemm(const float* __restrict__ bias, float* __restrict__ out) {
    extern __shared__ char smem[];
    uint32_t sb = smem_to_u32(smem);

    int tid = threadIdx.x;
    int wid = tid >> 5;
    int lane = tid & 31;
    int wm = wid >> 1;         // 0..1  (M group of 64)
    int wn = wid & 1;          // 0..1  (N group of 48)

    int lm  = lane >> 3;       // ldmatrix matrix index 0..3
    int lr8 = lane & 7;
    int rowoff = (lm & 1) * 8 + lr8;
    int coloff = (lm >> 1) * 8;    // halfs

    int tile = blockIdx.x;                 // 0..4095
    int w0 = (tile & 1) * 128;
    int h  = (tile >> 1) & 255;
    int b  = (tile >> 9) & 3;
    int nh = tile >> 11;                   // N half SLOWEST -> W locality
    int o0 = nh * 96;

    // ---- A fill: one base ptr + int32 per-segment offsets ----
    int ar = tid;                          // pixel row 0..127
    uint32_t aoff[5];
#pragma unroll
    for (int s = 0; s < 5; s++) {
        int dh = (s == 3) - (s == 4);
        int dw = (s == 1) - (s == 2);
        aoff[s] = (uint32_t)((((b * HP) + (h + 1 + dh)) * WP
                              + (w0 + ar + 1 + dw)) * CCH);
    }
    uint32_t a_smem = sb + ar * A_ROWB;

    // ---- B fragment base pointer (per lane) ----
    const __half* wf0 = g_wf + (size_t)(o0 + wn * 48 + (lane >> 2)) * KTOT
                        + (lane & 3) * 8;

    float acc[4][3][2][4] = {};

    auto issueA = [&](int it) {
        int seg = (it * 43691) >> 18;      // it/6 for it<30
        int c0 = (it - seg * 6) * 32;
        const char* ga = reinterpret_cast<const char*>(g_xh + aoff[seg] + c0);
        uint32_t sa = a_smem + (it & 3) * A_SZ;
#pragma unroll
        for (int j = 0; j < 4; j++)
            cp_async16(sa + j * 16, ga + j * 16);
    };

#pragma unroll
    for (int s = 0; s < STAGES - 1; s++) { issueA(s); CP_COMMIT(); }

#pragma unroll 1
    for (int it = 0; it < KITERS; ++it) {
        // B fragments for this iter: 6 x LDG.128, issued before the wait
        // so L2 latency overlaps CP_WAIT + barrier.
        uint32_t bf[3][2][4];
#pragma unroll
        for (int nj = 0; nj < 3; nj++)
#pragma unroll
            for (int hf = 0; hf < 2; hf++) {
                const uint4* pB = reinterpret_cast<const uint4*>(
                    wf0 + (size_t)(nj * 16 + hf * 8) * KTOT + it * 32);
                uint4 v = __ldg(pB);
                bf[nj][hf][0] = v.x; bf[nj][hf][1] = v.y;
                bf[nj][hf][2] = v.z; bf[nj][hf][3] = v.w;
            }

        CP_WAIT2();
        __syncthreads();   // stage it&3 ready; all warps done reading (it-1)&3

        if (it + STAGES - 1 < KITERS) issueA(it + STAGES - 1);
        CP_COMMIT();

        uint32_t Ab = sb + (it & 3) * A_SZ;

#pragma unroll
        for (int kk = 0; kk < 2; kk++) {
            // mi processed in halves of 2 to keep only 8 afr regs live
#pragma unroll
            for (int mh = 0; mh < 2; mh++) {
                uint32_t afr[2][4];
#pragma unroll
                for (int m2 = 0; m2 < 2; m2++) {
                    int row = wm * 64 + (mh * 2 + m2) * 16 + rowoff;
                    int col = kk * 16 + coloff;
                    ldsm4(afr[m2], Ab + row * A_ROWB + col * 2);
                }
#pragma unroll
                for (int m2 = 0; m2 < 2; m2++) {
                    int mi = mh * 2 + m2;
#pragma unroll
                    for (int nj = 0; nj < 3; nj++) {
                        mma16816(acc[mi][nj][0], afr[m2],
                                 bf[nj][0][kk * 2], bf[nj][0][kk * 2 + 1]);
                        mma16816(acc[mi][nj][1], afr[m2],
                                 bf[nj][1][kk * 2], bf[nj][1][kk * 2 + 1]);
                    }
                }
            }
        }
    }

    // ---- epilogue: direct STG (8 consecutive pixels x 4B per store row) ----
    int g8 = lane >> 2;       // 0..7 pixel sub-row
    int q  = lane & 3;        // o pair selector
    size_t out_hw = (size_t)h * WDIM + w0;
#pragma unroll
    for (int mi = 0; mi < 4; mi++) {
        int r0 = wm * 64 + mi * 16 + g8;
#pragma unroll
        for (int nj = 0; nj < 3; nj++)
#pragma unroll
            for (int hf = 0; hf < 2; hf++) {
                int o = o0 + wn * 48 + nj * 16 + hf * 8 + 2 * q;
                float bz0 = __ldg(bias + o);
                float bz1 = __ldg(bias + o + 1);
                float* p0 = out + ((size_t)(b * OCH + o)) * (HDIM * WDIM)
                            + out_hw;
                float* p1 = p0 + (size_t)(HDIM * WDIM);
                p0[r0]     = acc[mi][nj][hf][0] + bz0;
                p1[r0]     = acc[mi][nj][hf][1] + bz1;
                p0[r0 + 8] = acc[mi][nj][hf][2] + bz0;
                p1[r0 + 8] = acc[mi][nj][hf][3] + bz1;
            }
    }
}

// ---------------- launch ----------------

extern "C" void kernel_launch(void* const* d_in, const int* in_sizes, int n_in,
                              void* d_out, int out_size) {
    const float* x = (const float*)d_in[0];    // [4,192,256,256]
    const float* W = (const float*)d_in[1];    // [192, 960]
    const float* bias = (const float*)d_in[2]; // [192]
    float* out = (float*)d_out;

    prep_all<<<NB_ALL, 256>>>(x, W);

    cudaFuncSetAttribute(shiftconv_gemm,
                         cudaFuncAttributeMaxDynamicSharedMemorySize, SMEM_TOT);
    shiftconv_gemm<<<BATCH * HDIM * 2 * 2, 128, SMEM_TOT>>>(bias, out);
}

// round 17
// speedup vs baseline: 1.7504x; 1.0030x over previous
#include <cuda_runtime.h>
#include <cuda_fp16.h>
#include <cstdint>

// ============================================================
// ShiftConv (sm_103 non-'a' target): HMMA mma.sync fp16 GEMM.
// out[b,o,h,w] = bias[o] + sum_s sum_c W[o, s*192+c] * x[b,c,h+dh,w+dw]
// GEMM: C[pix, 192] = A[pix, 960] * W^T. A = shifted gather from padded
// pixel-major fp16 x (cp.async smem + ldmatrix). B = fragment-major W in
// gmem, 6x LDG.128 per warp-iter straight into mma layout.
// R17: GEMM = R10 verbatim (AT the HMMA.16816.F32 issue roofline,
// 0.25/cyc/SM = 638K cyc). Prep (at the LTS ceiling, ~6.8 TB/s eff)
// micro-consolidated: border zeroing vectorized to STG.128 (8x fewer
// stores/blocks), conflict-free permuted transpose unchanged.
// ============================================================

#define BATCH 4
#define CCH   192
#define HDIM  256
#define WDIM  256
#define HP    258
#define WP    258
#define OCH   192
#define KTOT  (5 * CCH)   // 960

static constexpr int XPAD_ELEMS = BATCH * HP * WP * CCH;

__device__ __align__(16) __half g_xh[XPAD_ELEMS];
// Fragment-major W: index = o*960 + it*32 + p*8 (halfs); 8 halfs cover
// k = it*32 + {2p,2p+1, 2p+8,2p+9, 2p+16,2p+17, 2p+24,2p+25}
__device__ __align__(16) __half g_wf[OCH * KTOT];

// ---------------- helpers ----------------

__device__ __forceinline__ uint32_t smem_to_u32(const void* p) {
    uint32_t a;
    asm("{ .reg .u64 t; cvta.to.shared.u64 t, %1; cvt.u32.u64 %0, t; }"
        : "=r"(a) : "l"(p));
    return a;
}

__device__ __forceinline__ void cp_async16(uint32_t saddr, const void* gaddr) {
    asm volatile("cp.async.cg.shared.global [%0], [%1], 16;"
                 :: "r"(saddr), "l"(gaddr));
}
#define CP_COMMIT() asm volatile("cp.async.commit_group;" ::: "memory")
#define CP_WAIT2()  asm volatile("cp.async.wait_group 2;" ::: "memory")

__device__ __forceinline__ void ldsm4(uint32_t* r, uint32_t addr) {
    asm volatile("ldmatrix.sync.aligned.m8n8.x4.shared.b16 {%0,%1,%2,%3}, [%4];"
                 : "=r"(r[0]), "=r"(r[1]), "=r"(r[2]), "=r"(r[3]) : "r"(addr));
}

__device__ __forceinline__ void mma16816(float* c, const uint32_t* a,
                                         uint32_t b0, uint32_t b1) {
    asm volatile(
        "mma.sync.aligned.m16n8k16.row.col.f32.f16.f16.f32 "
        "{%0,%1,%2,%3}, {%4,%5,%6,%7}, {%8,%9}, {%0,%1,%2,%3};"
        : "+f"(c[0]), "+f"(c[1]), "+f"(c[2]), "+f"(c[3])
        : "r"(a[0]), "r"(a[1]), "r"(a[2]), "r"(a[3]), "r"(b0), "r"(b1));
}

// ---------------- fused prep kernel ----------------
// blocks [0, NB_T): x transpose+convert (2 wblk x 6 cblk x 1024 bh)
// blocks [NB_T, NB_T+NB_B): border zeroing, uint4 (8-half) stores
//   4 lines x 258 px x 24 uint4 per batch = 24768; x4 b = 99072 -> 387 blks
// blocks [NB_T+NB_B, ..+NB_W): W fragment pack (90 x 256 = 23040)

static constexpr int NB_T = 12288;
static constexpr int NB_B = 387;
static constexpr int NB_W = 90;
static constexpr int NB_ALL = NB_T + NB_B + NB_W;
static constexpr int CCH4 = CCH / 8;     // 24 uint4 per border pixel

__global__ __launch_bounds__(256)
void prep_all(const float* __restrict__ x, const float* __restrict__ W) {
    __shared__ float4 tile4[32 * 33];    // row stride 33 chunks (132 floats)
    int blk = blockIdx.x;
    int tid = threadIdx.x;               // 256

    if (blk < NB_T) {
        // ---- transpose: blk = ((bh*6 + cblk) << 1) | wblk ----
        int wblk = blk & 1;
        int rest = blk >> 1;             // 0..6143
        int cblk = rest % 6;
        int bh   = rest / 6;             // 0..1023
        int b = bh >> 8, h = bh & 255;
        int w0 = wblk * 128, c0 = cblk * 32;
        int tx = tid & 31;               // w-quad 0..31
        int ty = tid >> 5;               // 0..7

        // write phase: channel row -> permuted smem row; STS.128,
        // per-8-lane phase chunks distinct mod 8 -> conflict-free.
#pragma unroll
        for (int i = 0; i < 4; i++) {
            int row = ty + i * 8;        // channel-in-tile 0..31
            float4 v = *reinterpret_cast<const float4*>(
                x + (((size_t)b * CCH + c0 + row) * HDIM + h) * WDIM
                  + w0 + tx * 4);
            int pr = ((row & 3) << 3) | (row >> 2);
            tile4[pr * 33 + tx] = v;
        }
        __syncthreads();

        // read phase: bank = (8*(lane&3) + (lane>>2) + const) mod 32 —
        // all 32 lanes distinct -> conflict-free scalar LDS.
        const float* tf = reinterpret_cast<const float*>(tile4);
#pragma unroll
        for (int j = 0; j < 2; j++) {
            int idx = tid + j * 256;     // 0..511
            int w  = idx >> 2;           // 0..127
            int cg = (idx & 3) * 8;      // 0,8,16,24
            float f[8];
#pragma unroll
            for (int i = 0; i < 8; i++) {
                int c = cg + i;
                int pr = ((c & 3) << 3) | (c >> 2);
                f[i] = tf[(pr * 33 + (w >> 2)) * 4 + (w & 3)];
            }
            __half2 p0 = __floats2half2_rn(f[0], f[1]);
            __half2 p1 = __floats2half2_rn(f[2], f[3]);
            __half2 p2 = __floats2half2_rn(f[4], f[5]);
            __half2 p3 = __floats2half2_rn(f[6], f[7]);
            size_t dst = (((size_t)b * HP + (h + 1)) * WP + (w0 + w + 1))
                         * CCH + c0 + cg;
            uint4 v;
            v.x = *reinterpret_cast<uint32_t*>(&p0);
            v.y = *reinterpret_cast<uint32_t*>(&p1);
            v.z = *reinterpret_cast<uint32_t*>(&p2);
            v.w = *reinterpret_cast<uint32_t*>(&p3);
            *reinterpret_cast<uint4*>(g_xh + dst) = v;
        }
    } else if (blk < NB_T + NB_B) {
        // ---- border zeroing: one uint4 (8 halfs) per slot ----
        const int per_b = 4 * WP * CCH4;          // 24768 uint4 per batch
        int i = (blk - NB_T) * 256 + tid;          // 0..99071
        if (i < BATCH * per_b) {
            int b = i / per_b;
            int r = i % per_b;
            int line = r / (WP * CCH4);
            int j = r % (WP * CCH4);
            int pos = j / CCH4;
            int cq = j % CCH4;
            int hh, ww;
            if      (line == 0) { hh = 0;      ww = pos; }
            else if (line == 1) { hh = HP - 1; ww = pos; }
            else if (line == 2) { hh = pos;    ww = 0;   }
            else                { hh = pos;    ww = WP - 1; }
            size_t dst = (((size_t)b * HP + hh) * WP + ww) * CCH + cq * 8;
            *reinterpret_cast<uint4*>(g_xh + dst) = make_uint4(0, 0, 0, 0);
        }
    } else {
        // ---- W fragment pack ----
        int i = (blk - NB_T - NB_B) * 256 + tid;   // 0..23039
        int p  = i & 3;
        int it = (i >> 2) % 30;
        int o  = i / 120;
        const float* src = W + (size_t)o * KTOT + it * 32 + p * 2;
        __half v[8];
#pragma unroll
        for (int q = 0; q < 4; q++) {
            v[q * 2]     = __float2half(src[q * 8]);
            v[q * 2 + 1] = __float2half(src[q * 8 + 1]);
        }
        *reinterpret_cast<uint4*>(g_wf + (size_t)o * KTOT + it * 32 + p * 8) =
            *reinterpret_cast<uint4*>(v);
    }
}

// ---------------- main GEMM kernel (R10, at HMMA roofline) ----------------
// CTA tile M=128 pixels x N=96 outputs, K=960, k-step 32, 4-stage cp.async
// for A. 128 threads = 4 warps 2(M)x2(N); warp tile 64x48. 3 CTAs/SM.

static constexpr int STAGES   = 4;
static constexpr int A_ROWB   = 80;                 // 40 halfs (32 + 8 pad)
static constexpr int A_SZ     = 128 * A_ROWB;       // 10240 B / stage
static constexpr int SMEM_TOT = STAGES * A_SZ;      // 40960
static constexpr int KITERS   = 30;

__global__ __launch_bounds__(128, 3)
void shiftconv_gemm(const float* __restrict__ bias, float* __restrict__ out) {
    extern __shared__ char smem[];
    uint32_t sb = smem_to_u32(smem);

    int tid = threadIdx.x;
    int wid = tid >> 5;
    int lane = tid & 31;
    int wm = wid >> 1;         // 0..1  (M group of 64)
    int wn = wid & 1;          // 0..1  (N group of 48)

    int lm  = lane >> 3;       // ldmatrix matrix index 0..3
    int lr8 = lane & 7;
    int rowoff = (lm & 1) * 8 + lr8;
    int coloff = (lm >> 1) * 8;    // halfs

    int tile = blockIdx.x;                 // 0..4095
    int w0 = (tile & 1) * 128;
    int h  = (tile >> 1) & 255;
    int b  = (tile >> 9) & 3;
    int nh = tile >> 11;                   // N half SLOWEST -> W locality
    int o0 = nh * 96;

    // ---- A fill: one base ptr + int32 per-segment offsets ----
    int ar = tid;                          // pixel row 0..127
    uint32_t aoff[5];
#pragma unroll
    for (int s = 0; s < 5; s++) {
        int dh = (s == 3) - (s == 4);
        int dw = (s == 1) - (s == 2);
        aoff[s] = (uint32_t)((((b * HP) + (h + 1 + dh)) * WP
                              + (w0 + ar + 1 + dw)) * CCH);
    }
    uint32_t a_smem = sb + ar * A_ROWB;

    // ---- B fragment base pointer (per lane) ----
    const __half* wf0 = g_wf + (size_t)(o0 + wn * 48 + (lane >> 2)) * KTOT
                        + (lane & 3) * 8;

    float acc[4][3][2][4] = {};

    auto issueA = [&](int it) {
        int seg = (it * 43691) >> 18;      // it/6 for it<30
        int c0 = (it - seg * 6) * 32;
        const char* ga = reinterpret_cast<const char*>(g_xh + aoff[seg] + c0);
        uint32_t sa = a_smem + (it & 3) * A_SZ;
#pragma unroll
        for (int j = 0; j < 4; j++)
            cp_async16(sa + j * 16, ga + j * 16);
    };

#pragma unroll
    for (int s = 0; s < STAGES - 1; s++) { issueA(s); CP_COMMIT(); }

#pragma unroll 1
    for (int it = 0; it < KITERS; ++it) {
        // B fragments for this iter: 6 x LDG.128, issued before the wait
        // so L2 latency overlaps CP_WAIT + barrier.
        uint32_t bf[3][2][4];
#pragma unroll
        for (int nj = 0; nj < 3; nj++)
#pragma unroll
            for (int hf = 0; hf < 2; hf++) {
                const uint4* pB = reinterpret_cast<const uint4*>(
                    wf0 + (size_t)(nj * 16 + hf * 8) * KTOT + it * 32);
                uint4 v = __ldg(pB);
                bf[nj][hf][0] = v.x; bf[nj][hf][1] = v.y;
                bf[nj][hf][2] = v.z; bf[nj][hf][3] = v.w;
            }

        CP_WAIT2();
        __syncthreads();   // stage it&3 ready; all warps done reading (it-1)&3

        if (it + STAGES - 1 < KITERS) issueA(it + STAGES - 1);
        CP_COMMIT();

        uint32_t Ab = sb + (it & 3) * A_SZ;

#pragma unroll
        for (int kk = 0; kk < 2; kk++) {
            // mi processed in halves of 2 to keep only 8 afr regs live
#pragma unroll
            for (int mh = 0; mh < 2; mh++) {
                uint32_t afr[2][4];
#pragma unroll
                for (int m2 = 0; m2 < 2; m2++) {
                    int row = wm * 64 + (mh * 2 + m2) * 16 + rowoff;
                    int col = kk * 16 + coloff;
                    ldsm4(afr[m2], Ab + row * A_ROWB + col * 2);
                }
#pragma unroll
                for (int m2 = 0; m2 < 2; m2++) {
                    int mi = mh * 2 + m2;
#pragma unroll
                    for (int nj = 0; nj < 3; nj++) {
                        mma16816(acc[mi][nj][0], afr[m2],
                                 bf[nj][0][kk * 2], bf[nj][0][kk * 2 + 1]);
                        mma16816(acc[mi][nj][1], afr[m2],
                                 bf[nj][1][kk * 2], bf[nj][1][kk * 2 + 1]);
                    }
                }
            }
        }
    }

    // ---- epilogue: direct STG (8 consecutive pixels x 4B per store row) ----
    int g8 = lane >> 2;       // 0..7 pixel sub-row
    int q  = lane & 3;        // o pair selector
    size_t out_hw = (size_t)h * WDIM + w0;
#pragma unroll
    for (int mi = 0; mi < 4; mi++) {
        int r0 = wm * 64 + mi * 16 + g8;
#pragma unroll
        for (int nj = 0; nj < 3; nj++)
#pragma unroll
            for (int hf = 0; hf < 2; hf++) {
                int o = o0 + wn * 48 + nj * 16 + hf * 8 + 2 * q;
                float bz0 = __ldg(bias + o);
                float bz1 = __ldg(bias + o + 1);
                float* p0 = out + ((size_t)(b * OCH + o)) * (HDIM * WDIM)
                            + out_hw;
                float* p1 = p0 + (size_t)(HDIM * WDIM);
                p0[r0]     = acc[mi][nj][hf][0] + bz0;
                p1[r0]     = acc[mi][nj][hf][1] + bz1;
                p0[r0 + 8] = acc[mi][nj][hf][2] + bz0;
                p1[r0 + 8] = acc[mi][nj][hf][3] + bz1;
            }
    }
}

// ---------------- launch ----------------

extern "C" void kernel_launch(void* const* d_in, const int* in_sizes, int n_in,
                              void* d_out, int out_size) {
    const float* x = (const float*)d_in[0];    // [4,192,256,256]
    const float* W = (const float*)d_in[1];    // [192, 960]
    const float* bias = (const float*)d_in[2]; // [192]
    float* out = (float*)d_out;

    prep_all<<<NB_ALL, 256>>>(x, W);

    cudaFuncSetAttribute(shiftconv_gemm,
                         cudaFuncAttributeMaxDynamicSharedMemorySize, SMEM_TOT);
    shiftconv_gemm<<<BATCH * HDIM * 2 * 2, 128, SMEM_TOT>>>(bias, out);
}